// round 2
// baseline (speedup 1.0000x reference)
#include <cuda_runtime.h>
#include <cstring>

// Closed-form: dynamics are affine, so 8 RK4 substeps collapse to a single
// affine map X_final = R8 * X0 + T*b (see host code). The kernel is a pure
// stream: coalesced float4 load -> smem -> per-env affine map -> smem ->
// coalesced float4 store.
//
// R2 change vs R1: 512 envs/block (2 envs/thread) to double per-thread load
// MLP (3 -> 6 outstanding LDG.128) and halve sync phases per byte.

struct Coef {
    float a01, a02, a12, a22;   // R8 entries
    float u0, u1, u2;           // c * T[:,2]  (coefficient of U)
    float d0, d1, d2;           // 9.81 * T[:,1] (gravity, z only)
};

#define THREADS        256
#define ENVS_PER_BLOCK 512
#define X_FLOATS (ENVS_PER_BLOCK * 9)   // 4608
#define U_FLOATS (ENVS_PER_BLOCK * 3)   // 1536
#define X_VEC4   (X_FLOATS / 4)         // 1152
#define U_VEC4   (U_FLOATS / 4)         // 384

__global__ void __launch_bounds__(THREADS)
pointmass_kernel(const float4* __restrict__ x0v,
                 const float4* __restrict__ uv,
                 float4* __restrict__ outv,
                 Coef C,
                 int n_x_vec4, int n_u_vec4)
{
    __shared__ float4 sx4[X_VEC4];
    __shared__ float4 su4[U_VEC4];
    float* sx = reinterpret_cast<float*>(sx4);
    float* su = reinterpret_cast<float*>(su4);

    const int tid = threadIdx.x;
    const size_t xbase = (size_t)blockIdx.x * X_VEC4;
    const size_t ubase = (size_t)blockIdx.x * U_VEC4;

    // ---- Load phase: issue ALL global loads back-to-back (max MLP), then sync.
    // X: 1152/256 = 4.5 iters ; U: 384/256 = 1.5 iters.
    float4 xr[4];
    float4 ur;
    #pragma unroll
    for (int k = 0; k < 4; k++) {
        size_t g = xbase + tid + k * THREADS;
        xr[k] = x0v[g];
    }
    float4 xtail;
    const bool has_xtail = (tid < X_VEC4 - 4 * THREADS);          // tid < 128
    if (has_xtail) xtail = x0v[xbase + tid + 4 * THREADS];
    ur = uv[ubase + tid];
    float4 utail;
    const bool has_utail = (tid < U_VEC4 - THREADS);              // tid < 128
    if (has_utail) utail = uv[ubase + tid + THREADS];

    #pragma unroll
    for (int k = 0; k < 4; k++) sx4[tid + k * THREADS] = xr[k];
    if (has_xtail) sx4[tid + 4 * THREADS] = xtail;
    su4[tid] = ur;
    if (has_utail) su4[tid + THREADS] = utail;

    __syncthreads();

    // ---- Compute phase: 2 envs per thread. smem stride 9/3 -> gcd(·,32)=1,
    // conflict-free.
    #pragma unroll
    for (int e = 0; e < 2; e++) {
        const int env = tid + e * THREADS;
        float* xp = sx + env * 9;
        const float* up = su + env * 3;

        #pragma unroll
        for (int f = 0; f < 3; f++) {
            float p = xp[f];
            float v = xp[f + 3];
            float a = xp[f + 6];
            float u = up[f];

            float np = fmaf(C.a01, v, fmaf(C.a02, a, fmaf(C.u0, u, p)));
            float nv = fmaf(C.a12, a, fmaf(C.u1, u, v));
            float na = fmaf(C.a22, a, C.u2 * u);
            if (f == 2) { np += C.d0; nv += C.d1; na += C.d2; }

            xp[f]     = np;
            xp[f + 3] = nv;
            xp[f + 6] = na;
        }
    }
    __syncthreads();

    // ---- Store phase: coalesced float4 stores, back-to-back.
    #pragma unroll
    for (int k = 0; k < 4; k++) {
        size_t g = xbase + tid + k * THREADS;
        outv[g] = sx4[tid + k * THREADS];
    }
    if (has_xtail) outv[xbase + tid + 4 * THREADS] = sx4[tid + 4 * THREADS];
}

// ---------------- host-side 3x3 double matrix helpers ----------------

static void m_mul(const double A[3][3], const double B[3][3], double C[3][3]) {
    double T[3][3];
    for (int i = 0; i < 3; i++)
        for (int j = 0; j < 3; j++) {
            double s = 0.0;
            for (int k = 0; k < 3; k++) s += A[i][k] * B[k][j];
            T[i][j] = s;
        }
    std::memcpy(C, T, sizeof(T));
}

static void m_addscaled(double A[3][3], const double B[3][3], double s) {
    for (int i = 0; i < 3; i++)
        for (int j = 0; j < 3; j++) A[i][j] += s * B[i][j];
}

extern "C" void kernel_launch(void* const* d_in, const int* in_sizes, int n_in,
                              void* d_out, int out_size)
{
    const float4* x0v = (const float4*)d_in[0];
    const float4* uv  = (const float4*)d_in[1];
    float4* outv      = (float4*)d_out;

    const int n_envs = in_sizes[0] / 9;   // 2097152 = 4096 * 512 (exact)

    // ---- build closed-form coefficients in double ----
    const double DT = 0.02;
    const double h  = DT / 8.0;
    const double c  = 0.5 / DT;     // LMBDA / DT = 25
    const double g  = 9.81;

    double I[3][3]  = {{1,0,0},{0,1,0},{0,0,1}};
    double hA[3][3] = {{0,h,0},{0,0,h},{0,0,-h*c}};

    double H2[3][3], H3[3][3], H4[3][3];
    m_mul(hA, hA, H2);
    m_mul(H2, hA, H3);
    m_mul(H3, hA, H4);

    double R[3][3];
    std::memcpy(R, I, sizeof(R));
    m_addscaled(R, hA, 1.0);
    m_addscaled(R, H2, 1.0/2.0);
    m_addscaled(R, H3, 1.0/6.0);
    m_addscaled(R, H4, 1.0/24.0);

    double S[3][3];
    std::memcpy(S, I, sizeof(S));
    m_addscaled(S, hA, 1.0/2.0);
    m_addscaled(S, H2, 1.0/6.0);
    m_addscaled(S, H3, 1.0/24.0);
    for (int i = 0; i < 3; i++)
        for (int j = 0; j < 3; j++) S[i][j] *= h;

    double P[3][3], Rk[3][3];
    std::memcpy(P, I, sizeof(P));
    std::memcpy(Rk, I, sizeof(Rk));
    for (int k = 1; k < 8; k++) {
        m_mul(Rk, R, Rk);
        m_addscaled(P, Rk, 1.0);
    }
    double R8[3][3];
    m_mul(Rk, R, R8);   // Rk holds R^7

    double T[3][3];
    m_mul(P, S, T);

    Coef C;
    C.a01 = (float)R8[0][1];
    C.a02 = (float)R8[0][2];
    C.a12 = (float)R8[1][2];
    C.a22 = (float)R8[2][2];
    C.u0  = (float)(c * T[0][2]);
    C.u1  = (float)(c * T[1][2]);
    C.u2  = (float)(c * T[2][2]);
    C.d0  = (float)(g * T[0][1]);
    C.d1  = (float)(g * T[1][1]);
    C.d2  = (float)(g * T[2][1]);

    const int n_x_vec4 = (n_envs * 9) / 4;
    const int n_u_vec4 = (n_envs * 3) / 4;
    const int blocks   = n_envs / ENVS_PER_BLOCK;   // 2^21 / 512 = 4096 exact

    pointmass_kernel<<<blocks, THREADS>>>(x0v, uv, outv, C, n_x_vec4, n_u_vec4);
}